// round 6
// baseline (speedup 1.0000x reference)
#include <cuda_runtime.h>
#include <math.h>

// Problem constants (shapes fixed by setup_inputs)
#define H      1024
#define E      8
#define TOPK   2
#define NTOK   4096          // 2 * 2048
#define NSEL   (TOPK * NTOK) // 8192 selections, k-major order

// Scratch (device globals: allocation-free rule)
__device__ int   g_top1[NTOK];
__device__ int   g_top2[NTOK];
__device__ float g_p1[NTOK];
__device__ float g_p2[NTOK];
__device__ int   g_sel_idx[NSEL];   // flat index into cb region, -1 = dropped
__device__ float g_sel_p[NSEL];
__device__ float g_used[E];

// ---------------------------------------------------------------------------
// Gate kernel: logits = x @ w_g^T, top-2, 2-way softmax.
// 8 warps/block, 4 tokens/warp (weight LDS amortized 4x), grid = 128.
// ---------------------------------------------------------------------------
__global__ __launch_bounds__(256) void k_gate(const float* __restrict__ x,
                                              const float* __restrict__ wg) {
    __shared__ float s_wg[E * H];   // 32 KB
    for (int i = threadIdx.x; i < E * H; i += 256)
        s_wg[i] = wg[i];
    __syncthreads();

    int warp = threadIdx.x >> 5;
    int lane = threadIdx.x & 31;
    int t0 = (blockIdx.x * 8 + warp) * 4;       // 4 consecutive tokens

    float acc[4][E];
    #pragma unroll
    for (int t = 0; t < 4; t++)
        #pragma unroll
        for (int e = 0; e < E; e++) acc[t][e] = 0.f;

    #pragma unroll
    for (int c = 0; c < H / 128; c++) {          // 8 chunks of 32*float4
        int idx4 = c * 32 + lane;
        float4 xv[4];
        #pragma unroll
        for (int t = 0; t < 4; t++)
            xv[t] = reinterpret_cast<const float4*>(x + (size_t)(t0 + t) * H)[idx4];
        int base = idx4 * 4;
        #pragma unroll
        for (int e = 0; e < E; e++) {
            float4 wv = *reinterpret_cast<const float4*>(&s_wg[e * H + base]);
            #pragma unroll
            for (int t = 0; t < 4; t++)
                acc[t][e] += xv[t].x * wv.x + xv[t].y * wv.y
                           + xv[t].z * wv.z + xv[t].w * wv.w;
        }
    }

    #pragma unroll
    for (int t = 0; t < 4; t++)
        #pragma unroll
        for (int e = 0; e < E; e++)
            #pragma unroll
            for (int off = 16; off > 0; off >>= 1)
                acc[t][e] += __shfl_xor_sync(0xffffffffu, acc[t][e], off);

    if (lane < 4) {
        int token = t0 + lane;
        float l[E];
        #pragma unroll
        for (int e = 0; e < E; e++) l[e] = acc[lane][e];
        int   i1 = 0; float l1 = l[0];
        #pragma unroll
        for (int e = 1; e < E; e++)
            if (l[e] > l1) { l1 = l[e]; i1 = e; }
        int   i2 = -1; float l2 = -INFINITY;
        #pragma unroll
        for (int e = 0; e < E; e++)
            if (e != i1 && l[e] > l2) { l2 = l[e]; i2 = e; }
        float e2 = expf(l2 - l1);          // l1 >= l2
        float inv = 1.0f / (1.0f + e2);
        g_top1[token] = i1;
        g_top2[token] = i2;
        g_p1[token]   = inv;
        g_p2[token]   = e2 * inv;
    }
}

// ---------------------------------------------------------------------------
// Rank kernel: 8 warps, ballot-based per-expert prefix ranks, two passes.
// Selection order is k-major: s = k*NTOK + n.
// ---------------------------------------------------------------------------
__global__ __launch_bounds__(256) void k_rank(int C) {
    const int tid  = threadIdx.x;
    const int warp = tid >> 5;
    const int lane = tid & 31;
    const unsigned lt = (1u << lane) - 1u;

    __shared__ int s_tot[8][E];
    __shared__ int s_off[8][E];

    // Pass 1: per-warp per-expert counts over 1024 consecutive selections.
    int run[E];
    #pragma unroll
    for (int e = 0; e < E; e++) run[e] = 0;
    for (int i = 0; i < 32; i++) {
        int s = warp * 1024 + i * 32 + lane;
        int n = s & (NTOK - 1);
        int e = (s >> 12) ? g_top2[n] : g_top1[n];
        #pragma unroll
        for (int eid = 0; eid < E; eid++) {
            unsigned b = __ballot_sync(0xffffffffu, e == eid);
            run[eid] += __popc(b);
        }
    }
    if (lane < E) {
        int v = 0;
        #pragma unroll
        for (int eid = 0; eid < E; eid++) if (lane == eid) v = run[eid];
        s_tot[warp][lane] = v;
    }
    __syncthreads();

    // Cross-warp exclusive scan (64 values) + grand totals.
    if (tid < 64) {
        int w = tid >> 3, e = tid & 7;
        int o = 0;
        for (int wp = 0; wp < w; wp++) o += s_tot[wp][e];
        s_off[w][e] = o;
        if (w == 7) {
            int total = o + s_tot[7][e];
            g_used[e] = (float)(total < C ? total : C);
        }
    }
    __syncthreads();

    // Pass 2: replay, emit (flat index, prob).
    #pragma unroll
    for (int e = 0; e < E; e++) run[e] = 0;
    for (int i = 0; i < 32; i++) {
        int s = warp * 1024 + i * 32 + lane;
        int n = s & (NTOK - 1);
        int k = s >> 12;
        int e = k ? g_top2[n] : g_top1[n];
        float p = k ? g_p2[n] : g_p1[n];
        int myrank = 0;
        #pragma unroll
        for (int eid = 0; eid < E; eid++) {
            unsigned b = __ballot_sync(0xffffffffu, e == eid);
            if (e == eid) myrank = run[eid] + __popc(b & lt);
            run[eid] += __popc(b);
        }
        int rank = s_off[warp][e] + myrank;
        g_sel_idx[s] = (rank < C) ? ((n * E + e) * C + rank) : -1;
        g_sel_p[s]   = p;
    }
}

// ---------------------------------------------------------------------------
// Scatter kernel: 8192 predicated pairs + 8 counts.
// ---------------------------------------------------------------------------
__global__ __launch_bounds__(1024) void k_scatter(float* __restrict__ out,
                                                  int N, int C) {
    int s = blockIdx.x * blockDim.x + threadIdx.x;
    float* cb  = out + E;
    float* msk = cb + (size_t)N * E * C;
    if (s < NSEL) {
        int idx = g_sel_idx[s];
        if (idx >= 0) {
            float p = g_sel_p[s];
            cb[idx]  = p;
            msk[idx] = 1.0f;
        }
    }
    if (blockIdx.x == 0 && threadIdx.x < E)
        out[threadIdx.x] = g_used[threadIdx.x];
}

// ---------------------------------------------------------------------------
extern "C" void kernel_launch(void* const* d_in, const int* in_sizes, int n_in,
                              void* d_out, int out_size) {
    const float* x  = (const float*)d_in[0];   // [2,2048,1024]
    const float* wg = (const float*)d_in[1];   // [8,1024]

    int N = in_sizes[0] / H;                           // 4096
    int cap = (int)(TOPK * 2.0 * N / E);               // 2048
    if (cap < 4) cap = 4;

    // Gate + rank don't touch d_out; memset (the ~62us DRAM floor) last,
    // directly ahead of the scatter that depends on it.
    k_gate<<<NTOK / 32, 256>>>(x, wg);
    k_rank<<<1, 256>>>(cap);

    cudaMemsetAsync(d_out, 0, (size_t)out_size * sizeof(float), 0);

    k_scatter<<<NSEL / 1024, 1024>>>((float*)d_out, N, cap);
}

// round 7
// speedup vs baseline: 1.5208x; 1.5208x over previous
#include <cuda_runtime.h>
#include <math.h>

// Problem constants (shapes fixed by setup_inputs)
#define H      1024
#define E      8
#define TOPK   2
#define NTOK   4096          // 2 * 2048
#define NSEL   (TOPK * NTOK) // 8192 selections, k-major order

// Scratch (device globals: allocation-free rule)
__device__ int   g_top1[NTOK];
__device__ int   g_top2[NTOK];
__device__ float g_p1[NTOK];
__device__ float g_p2[NTOK];

// ---------------------------------------------------------------------------
// Gate kernel: logits = x @ w_g^T, top-2, 2-way softmax.
// One warp per 2 tokens, weights read via __ldg (L1-resident, no smem, no bar).
// grid = 256 blocks x 8 warps = 2048 warps.
// ---------------------------------------------------------------------------
__global__ __launch_bounds__(256) void k_gate(const float* __restrict__ x,
                                              const float* __restrict__ wg) {
    int warp = threadIdx.x >> 5;
    int lane = threadIdx.x & 31;
    int t0 = (blockIdx.x * 8 + warp) * 2;       // 2 consecutive tokens

    const float4* wg4 = reinterpret_cast<const float4*>(wg);   // [E][256]
    const float4* x0  = reinterpret_cast<const float4*>(x + (size_t)t0 * H);
    const float4* x1  = reinterpret_cast<const float4*>(x + (size_t)(t0 + 1) * H);

    float acc0[E], acc1[E];
    #pragma unroll
    for (int e = 0; e < E; e++) { acc0[e] = 0.f; acc1[e] = 0.f; }

    #pragma unroll
    for (int c = 0; c < H / 128; c++) {          // 8 chunks of 32*float4
        int idx4 = c * 32 + lane;
        float4 xa = x0[idx4];
        float4 xb = x1[idx4];
        #pragma unroll
        for (int e = 0; e < E; e++) {
            float4 wv = __ldg(&wg4[e * (H / 4) + idx4]);
            acc0[e] += xa.x * wv.x + xa.y * wv.y + xa.z * wv.z + xa.w * wv.w;
            acc1[e] += xb.x * wv.x + xb.y * wv.y + xb.z * wv.z + xb.w * wv.w;
        }
    }

    #pragma unroll
    for (int e = 0; e < E; e++) {
        #pragma unroll
        for (int off = 16; off > 0; off >>= 1) {
            acc0[e] += __shfl_xor_sync(0xffffffffu, acc0[e], off);
            acc1[e] += __shfl_xor_sync(0xffffffffu, acc1[e], off);
        }
    }

    if (lane < 2) {
        int token = t0 + lane;
        float l[E];
        #pragma unroll
        for (int e = 0; e < E; e++) l[e] = lane ? acc1[e] : acc0[e];
        int   i1 = 0; float l1 = l[0];
        #pragma unroll
        for (int e = 1; e < E; e++)
            if (l[e] > l1) { l1 = l[e]; i1 = e; }
        int   i2 = -1; float l2 = -INFINITY;
        #pragma unroll
        for (int e = 0; e < E; e++)
            if (e != i1 && l[e] > l2) { l2 = l[e]; i2 = e; }
        float e2 = expf(l2 - l1);          // l1 >= l2
        float inv = 1.0f / (1.0f + e2);
        g_top1[token] = i1;
        g_top2[token] = i2;
        g_p1[token]   = inv;
        g_p2[token]   = e2 * inv;
    }
}

// ---------------------------------------------------------------------------
// Fused rank + scatter: one block, 32 warps. Ballot-based per-expert prefix
// ranks over the k-major selection sequence; writes nonzeros + used_capacity
// straight into out (runs after the memset).
// ---------------------------------------------------------------------------
__global__ __launch_bounds__(1024) void k_rank_scatter(float* __restrict__ out,
                                                       int N, int C) {
    const int tid  = threadIdx.x;
    const int warp = tid >> 5;           // 0..31, owns selections [warp*256, +256)
    const int lane = tid & 31;
    const unsigned lt = (1u << lane) - 1u;

    __shared__ int s_tot[32][E];
    __shared__ int s_off[32][E];

    // Pass 1: per-warp per-expert counts over 256 consecutive selections.
    int run[E];
    #pragma unroll
    for (int e = 0; e < E; e++) run[e] = 0;
    #pragma unroll
    for (int i = 0; i < 8; i++) {
        int s = warp * 256 + i * 32 + lane;
        int n = s & (NTOK - 1);
        int e = (s >> 12) ? g_top2[n] : g_top1[n];
        #pragma unroll
        for (int eid = 0; eid < E; eid++)
            run[eid] += __popc(__ballot_sync(0xffffffffu, e == eid));
    }
    if (lane < E) {
        int v = 0;
        #pragma unroll
        for (int eid = 0; eid < E; eid++) if (lane == eid) v = run[eid];
        s_tot[warp][lane] = v;
    }
    __syncthreads();

    // Cross-warp exclusive scan: warp e (e<8) scans the 32 per-warp counts.
    if (warp < E) {
        int v = s_tot[lane][warp];
        int inc = v;
        #pragma unroll
        for (int off = 1; off < 32; off <<= 1) {
            int u = __shfl_up_sync(0xffffffffu, inc, off);
            if (lane >= off) inc += u;
        }
        s_off[lane][warp] = inc - v;     // exclusive prefix
        if (lane == 31) {
            int total = inc;
            out[warp] = (float)(total < C ? total : C);   // used_capacity
        }
    }
    __syncthreads();

    // Pass 2: replay, scatter directly into out.
    float* cb  = out + E;
    float* msk = cb + (size_t)N * E * C;
    #pragma unroll
    for (int e = 0; e < E; e++) run[e] = 0;
    #pragma unroll
    for (int i = 0; i < 8; i++) {
        int s = warp * 256 + i * 32 + lane;
        int n = s & (NTOK - 1);
        int k = s >> 12;
        int e = k ? g_top2[n] : g_top1[n];
        float p = k ? g_p2[n] : g_p1[n];
        int myrank = 0;
        #pragma unroll
        for (int eid = 0; eid < E; eid++) {
            unsigned b = __ballot_sync(0xffffffffu, e == eid);
            if (e == eid) myrank = run[eid] + __popc(b & lt);
            run[eid] += __popc(b);
        }
        int rank = s_off[warp][e] + myrank;
        if (rank < C) {
            int idx = (n * E + e) * C + rank;    // < 67M, fits int
            cb[idx]  = p;
            msk[idx] = 1.0f;
        }
    }
}

// ---------------------------------------------------------------------------
extern "C" void kernel_launch(void* const* d_in, const int* in_sizes, int n_in,
                              void* d_out, int out_size) {
    const float* x  = (const float*)d_in[0];   // [2,2048,1024]
    const float* wg = (const float*)d_in[1];   // [8,1024]

    int N = in_sizes[0] / H;                           // 4096
    int cap = (int)(TOPK * 2.0 * N / E);               // 2048
    if (cap < 4) cap = 4;

    k_gate<<<NTOK / 16, 256>>>(x, wg);

    // Zero the whole (poisoned) output: the DRAM-write floor (~62us).
    cudaMemsetAsync(d_out, 0, (size_t)out_size * sizeof(float), 0);

    k_rank_scatter<<<1, 1024>>>((float*)d_out, N, cap);
}